// round 4
// baseline (speedup 1.0000x reference)
#include <cuda_runtime.h>
#include <math.h>

typedef unsigned long long u64;

#define NPQ  45
#define NPP  2025
#define NB   16
#define NTOT 32400

/* ================= K1 ================= */
#define T1   256
#define GP1  4
#define HALF1 4050            /* 8100 CTAs in two launches */

#define K1_RAW   0            /* 768   : [3][4][64]            */
#define K1_RS    768          /* 3468  : [3][4][289] 17x17 pad */
#define K1_ACT1  4236         /* 10368 : [32][4][81] 9x9 pad   */
#define K1_W1    14604        /* 864                            */
#define K1_W2    15468        /* 4096  : tap double buffer      */
#define K1_B     19564        /* 96    : b1,b2                  */
#define K1_FLOATS 19664
#define K1_BYTES (K1_FLOATS*4)

/* ================= K2 ================= */
#define T2   256
#define PG2  32
#define NBLK2 ((NTOT + PG2 - 1) / PG2)   /* 1013 */

#define K2_A     0            /* 16384 : act2 half [32pat][32ic][16]; reused wd/cx */
#define K2_W3    16384        /* 8192  : w3 slice double buffer  */
#define K2_ACT3  24576        /* 16384 : [32pat][512]            */
#define K2_VT    40960        /* 2048  : v transposed [64e][32p] */
#define K2_B3    43008        /* 128 */
#define K2_BD    43136        /* 64  */
#define K2_CW    43200        /* 128 */
#define K2_VN2   43328        /* 32  */
#define K2_FLOATS 43360
#define K2_BYTES (K2_FLOATS*4)

__device__ float g_ysum[NB * 128];
__device__ float g_act2[(size_t)(NTOT + PG2) * 1024];

/* ---- packed fp32x2 helpers ---- */
__device__ __forceinline__ u64 pack2(float lo, float hi) {
    u64 r; asm("mov.b64 %0, {%1, %2};" : "=l"(r) : "f"(lo), "f"(hi)); return r;
}
__device__ __forceinline__ void unpack2(u64 v, float& lo, float& hi) {
    asm("mov.b64 {%0, %1}, %2;" : "=f"(lo), "=f"(hi) : "l"(v));
}
__device__ __forceinline__ void fma2(u64& d, u64 a, u64 b) {
    asm("fma.rn.f32x2 %0, %1, %2, %0;" : "+l"(d) : "l"(a), "l"(b));
}

__device__ __forceinline__ void cp16(float* dst, const float* src) {
    unsigned s = (unsigned)__cvta_generic_to_shared(dst);
    asm volatile("cp.async.cg.shared.global [%0], [%1], 16;\n" :: "r"(s), "l"(src));
}
__device__ __forceinline__ void cp_commit() { asm volatile("cp.async.commit_group;\n"); }
__device__ __forceinline__ void cp_wait0()  { asm volatile("cp.async.wait_group 0;\n"); }

/* jax.image.resize 'linear' 8->16 */
__device__ __forceinline__ void rtab(int i, int& a0, int& a1, float& w0, float& w1) {
    if (i == 0)       { a0 = 0; a1 = 0; w0 = 1.f;   w1 = 0.f;   }
    else if (i == 15) { a0 = 7; a1 = 7; w0 = 1.f;   w1 = 0.f;   }
    else if (i & 1)   { int m = i >> 1; a0 = m;     a1 = m + 1; w0 = 0.75f; w1 = 0.25f; }
    else              { int m = i >> 1; a0 = m - 1; a1 = m;     w0 = 0.25f; w1 = 0.75f; }
}

/* ========== K1: gather + resize + conv1 + conv2 -> g_act2 ========== */
__global__ __launch_bounds__(T1, 2)
void k1_kernel(const float* __restrict__ images,
               const float* __restrict__ w1, const float* __restrict__ b1,
               const float* __restrict__ w2, const float* __restrict__ b2,
               int blk0)
{
    extern __shared__ float sm[];
    const int tid = threadIdx.x;
    const int g0  = (blk0 + blockIdx.x) * GP1;

    for (int i = tid; i < 864; i += T1) sm[K1_W1 + i] = w1[i];
    if (tid < 32) sm[K1_B + tid]      = b1[tid];
    if (tid < 64) sm[K1_B + 32 + tid] = b2[tid];
    /* zero rs + act1 (covers SAME padding) */
    for (int i = tid; i < (K1_W1 - K1_RS) / 4; i += T1)
        ((float4*)(sm + K1_RS))[i] = make_float4(0.f, 0.f, 0.f, 0.f);

    /* raw gather: [c][p][64] */
    for (int i = tid; i < 768; i += T1) {
        int c = i >> 8, rem = i & 255, p = rem >> 6, r = rem & 63;
        int iy = r >> 3, ix = r & 7;
        int g = g0 + p, b = g / NPP, pp = g % NPP;
        int py = pp / NPQ, px = pp % NPQ;
        sm[K1_RAW + i] = images[((b * 96 + py * 2 + iy) * 96 + px * 2 + ix) * 3 + c];
    }
    __syncthreads();

    /* resize 8x8 -> 16x16 into [c][p][289] */
    for (int i = tid; i < 3072; i += T1) {
        int c = i >> 10, rem = i & 1023, p = rem >> 8, r = rem & 255;
        int oy = r >> 4, ox = r & 15;
        int ay0, ay1, ax0, ax1; float wy0, wy1, wx0, wx1;
        rtab(oy, ay0, ay1, wy0, wy1);
        rtab(ox, ax0, ax1, wx0, wx1);
        const float* rp = sm + K1_RAW + c * 256 + p * 64;
        float v00 = rp[ay0 * 8 + ax0], v01 = rp[ay0 * 8 + ax1];
        float v10 = rp[ay1 * 8 + ax0], v11 = rp[ay1 * 8 + ax1];
        sm[K1_RS + c * 1156 + p * 289 + oy * 17 + ox] =
            wy0 * (wx0 * v00 + wx1 * v01) + wy1 * (wx0 * v10 + wx1 * v11);
    }
    __syncthreads();

    /* conv1: M=256(4p*8oy*8ox) N=32, TM=4(ox) TN=8 */
    {
        const int mt = tid >> 2, ng = tid & 3;
        const int p = mt >> 4, oy = (mt >> 1) & 7, oxp = mt & 1;
        u64 acc[4][4];
        #pragma unroll
        for (int i = 0; i < 4; i++)
            #pragma unroll
            for (int j = 0; j < 4; j++) acc[i][j] = 0ull;

        #pragma unroll 1
        for (int t = 0; t < 9; t++) {
            int ky = t / 3, kx = t - ky * 3;
            #pragma unroll
            for (int c = 0; c < 3; c++) {
                const float* ap = sm + K1_RS + c * 1156 + p * 289
                                  + (2 * oy + ky) * 17 + kx + 8 * oxp;
                u64 aa[4];
                #pragma unroll
                for (int i = 0; i < 4; i++) { float a = ap[2 * i]; aa[i] = pack2(a, a); }
                const u64* wp = (const u64*)(sm + K1_W1 + (t * 3 + c) * 32 + ng * 8);
                u64 b0 = wp[0], b1v = wp[1], b2v = wp[2], b3v = wp[3];
                #pragma unroll
                for (int i = 0; i < 4; i++) {
                    fma2(acc[i][0], aa[i], b0);
                    fma2(acc[i][1], aa[i], b1v);
                    fma2(acc[i][2], aa[i], b2v);
                    fma2(acc[i][3], aa[i], b3v);
                }
            }
        }
        #pragma unroll
        for (int j = 0; j < 4; j++) {
            int oc0 = ng * 8 + 2 * j;
            float bi0 = sm[K1_B + oc0], bi1 = sm[K1_B + oc0 + 1];
            float* o0 = sm + K1_ACT1 + oc0 * 324 + p * 81 + oy * 9 + oxp * 4;
            float* o1 = o0 + 324;
            #pragma unroll
            for (int i = 0; i < 4; i++) {
                float lo, hi; unpack2(acc[i][j], lo, hi);
                o0[i] = fmaxf(lo + bi0, 0.f);
                o1[i] = fmaxf(hi + bi1, 0.f);
            }
        }
    }
    __syncthreads();

    /* conv2: M=64(4p*4oy*4ox) N=64, TM=2(ox) TN=8; w2 per-tap double buffer */
    {
        const int mt = tid >> 3, ng = tid & 7;
        const int p = mt >> 3, oy = (mt >> 1) & 3, oxp2 = mt & 1;
        u64 acc[2][4];
        #pragma unroll
        for (int i = 0; i < 2; i++)
            #pragma unroll
            for (int j = 0; j < 4; j++) acc[i][j] = 0ull;

        for (int i = tid; i < 512; i += T1) cp16(sm + K1_W2 + i * 4, w2 + i * 4);
        cp_commit();

        #pragma unroll 1
        for (int t = 0; t < 9; t++) {
            cp_wait0();
            __syncthreads();
            if (t < 8) {
                for (int i = tid; i < 512; i += T1)
                    cp16(sm + K1_W2 + ((t + 1) & 1) * 2048 + i * 4,
                         w2 + (t + 1) * 2048 + i * 4);
                cp_commit();
            }
            int ky = t / 3, kx = t - ky * 3;
            const float* wb = sm + K1_W2 + (t & 1) * 2048;
            const float* ab = sm + K1_ACT1 + p * 81 + (2 * oy + ky) * 9 + kx + 4 * oxp2;
            #pragma unroll 4
            for (int ic = 0; ic < 32; ic++) {
                float a0 = ab[ic * 324], a1 = ab[ic * 324 + 2];
                u64 aa0 = pack2(a0, a0), aa1 = pack2(a1, a1);
                const u64* wp = (const u64*)(wb + ic * 64 + ng * 8);
                u64 b0 = wp[0], b1v = wp[1], b2v = wp[2], b3v = wp[3];
                fma2(acc[0][0], aa0, b0);  fma2(acc[1][0], aa1, b0);
                fma2(acc[0][1], aa0, b1v); fma2(acc[1][1], aa1, b1v);
                fma2(acc[0][2], aa0, b2v); fma2(acc[1][2], aa1, b2v);
                fma2(acc[0][3], aa0, b3v); fma2(acc[1][3], aa1, b3v);
            }
        }
        /* write compact act2 [patch][oc][16] */
        unsigned patch = (unsigned)(g0 + p);
        float* gbase = g_act2 + (size_t)patch * 1024 + oy * 4 + 2 * oxp2;
        #pragma unroll
        for (int j = 0; j < 4; j++) {
            int oc0 = ng * 8 + 2 * j;
            float bi0 = sm[K1_B + 32 + oc0], bi1 = sm[K1_B + 32 + oc0 + 1];
            float l0, h0, l1, h1;
            unpack2(acc[0][j], l0, h0);
            unpack2(acc[1][j], l1, h1);
            float2 v0 = make_float2(fmaxf(l0 + bi0, 0.f), fmaxf(l1 + bi0, 0.f));
            float2 v1 = make_float2(fmaxf(h0 + bi1, 0.f), fmaxf(h1 + bi1, 0.f));
            *(float2*)(gbase + oc0 * 16)       = v0;
            *(float2*)(gbase + (oc0 + 1) * 16) = v1;
        }
    }
}

/* ========== K2: conv3 + dense + head ========== */
__global__ __launch_bounds__(T2, 1)
void k2_kernel(const float* __restrict__ w3, const float* __restrict__ b3,
               const float* __restrict__ wd, const float* __restrict__ bd,
               const float* __restrict__ c_x, const float* __restrict__ comp_w,
               const float* __restrict__ sigma)
{
    extern __shared__ float sm[];
    const int tid = threadIdx.x;
    const int pbase = blockIdx.x * PG2;

    if (tid < 128) sm[K2_B3 + tid] = b3[tid];
    if (tid < 64)  sm[K2_BD + tid] = bd[tid];
    if (tid < 128) sm[K2_CW + tid] = comp_w[tid];

    /* ---- conv3: M=128 (32p*4px), N=128, K=576; taps unrolled w/ padding pruning ---- */
    const int mt = tid >> 4, ng = tid & 15;
    u64 acc[2][4][4];
    #pragma unroll
    for (int pa = 0; pa < 2; pa++)
        #pragma unroll
        for (int px = 0; px < 4; px++)
            #pragma unroll
            for (int j = 0; j < 4; j++) acc[pa][px][j] = 0ull;

    #pragma unroll 1
    for (int ih = 0; ih < 2; ih++) {
        __syncthreads();
        /* stage act half: [pat][32ic][16] = 16384 floats */
        for (int i = tid; i < 4096; i += T2) {
            int pat = i >> 7, off = i & 127;
            cp16(sm + K2_A + pat * 512 + off * 4,
                 g_act2 + (size_t)(pbase + pat) * 1024 + ih * 512 + off * 4);
        }
        for (int i = tid; i < 1024; i += T2)
            cp16(sm + K2_W3 + i * 4, w3 + ih * 4096 + i * 4);
        cp_commit();

        #pragma unroll
        for (int t = 0; t < 9; t++) {
            cp_wait0();
            __syncthreads();
            if (t < 8) {
                for (int i = tid; i < 1024; i += T2)
                    cp16(sm + K2_W3 + ((t + 1) & 1) * 4096 + i * 4,
                         w3 + (t + 1) * 8192 + ih * 4096 + i * 4);
                cp_commit();
            }
            const int ky = t / 3, kx = t % 3;
            const float* wb = sm + K2_W3 + (t & 1) * 4096;
            #pragma unroll 2
            for (int icl = 0; icl < 32; icl++) {
                const u64* wp = (const u64*)(wb + icl * 128 + ng * 8);
                u64 b0 = wp[0], b1v = wp[1], b2v = wp[2], b3v = wp[3];
                #pragma unroll
                for (int pa = 0; pa < 2; pa++) {
                    const float* ap = sm + K2_A + (2 * mt + pa) * 512 + icl * 16;
                    #pragma unroll
                    for (int px = 0; px < 4; px++) {
                        const int iy = 2 * (px >> 1) + ky, ix = 2 * (px & 1) + kx;
                        if (iy < 4 && ix < 4) {          /* compile-time pruned */
                            float a = ap[iy * 4 + ix];
                            u64 aa = pack2(a, a);
                            fma2(acc[pa][px][0], aa, b0);
                            fma2(acc[pa][px][1], aa, b1v);
                            fma2(acc[pa][px][2], aa, b2v);
                            fma2(acc[pa][px][3], aa, b3v);
                        }
                    }
                }
            }
        }
    }
    __syncthreads();

    /* conv3 epilogue -> act3 [pat][px*128+oc] */
    #pragma unroll
    for (int pa = 0; pa < 2; pa++)
        #pragma unroll
        for (int px = 0; px < 4; px++)
            #pragma unroll
            for (int j = 0; j < 4; j++) {
                int oc0 = ng * 8 + 2 * j;
                float lo, hi; unpack2(acc[pa][px][j], lo, hi);
                float* o = sm + K2_ACT3 + (2 * mt + pa) * 512 + px * 128 + oc0;
                o[0] = fmaxf(lo + sm[K2_B3 + oc0], 0.f);
                o[1] = fmaxf(hi + sm[K2_B3 + oc0 + 1], 0.f);
            }

    /* ---- dense 512->64: wd 64-row chunks double buffered in s_a ---- */
    {
        const int dp = tid >> 3, eg = tid & 7;
        u64 vacc[4] = {0ull, 0ull, 0ull, 0ull};

        for (int i = tid; i < 1024; i += T2) cp16(sm + K2_A + i * 4, wd + i * 4);
        cp_commit();

        #pragma unroll 1
        for (int c = 0; c < 8; c++) {
            cp_wait0();
            __syncthreads();
            if (c < 7) {
                for (int i = tid; i < 1024; i += T2)
                    cp16(sm + K2_A + ((c + 1) & 1) * 4096 + i * 4,
                         wd + (c + 1) * 4096 + i * 4);
                cp_commit();
            }
            const float* xp = sm + K2_ACT3 + dp * 512 + c * 64;
            const float* wp = sm + K2_A + (c & 1) * 4096;
            #pragma unroll 8
            for (int k = 0; k < 64; k++) {
                float x = xp[k];
                u64 xx = pack2(x, x);
                const u64* ww = (const u64*)(wp + k * 64 + eg * 8);
                fma2(vacc[0], xx, ww[0]);
                fma2(vacc[1], xx, ww[1]);
                fma2(vacc[2], xx, ww[2]);
                fma2(vacc[3], xx, ww[3]);
            }
        }
        #pragma unroll
        for (int j = 0; j < 4; j++) {
            int e0 = eg * 8 + 2 * j;
            float lo, hi; unpack2(vacc[j], lo, hi);
            sm[K2_VT + e0 * 32 + dp]       = lo + sm[K2_BD + e0];
            sm[K2_VT + (e0 + 1) * 32 + dp] = hi + sm[K2_BD + e0 + 1];
        }
    }
    __syncthreads();

    /* vn2 + stage c_x (stride 65) into s_a */
    if (tid < 32) {
        float a = 0.f;
        #pragma unroll 8
        for (int e = 0; e < 64; e++) {
            float v = sm[K2_VT + e * 32 + tid];
            a = fmaf(v, v, a);
        }
        sm[K2_VN2 + tid] = a;
    }
    for (int i = tid; i < 8192; i += T2) {
        int k = i >> 6, e = i & 63;
        sm[K2_A + k * 65 + e] = c_x[i];
    }
    __syncthreads();

    /* ---- head: 128 k x 32 patches ---- */
    {
        float inv_s2 = 1.f / (sigma[0] * sigma[0]);
        const int k = tid & 127, pg = tid >> 7;
        const int pl0 = pg * 16;
        u64 d[8];
        #pragma unroll
        for (int i = 0; i < 8; i++)
            d[i] = pack2(sm[K2_VN2 + pl0 + 2 * i], sm[K2_VN2 + pl0 + 2 * i + 1]);
        const float* ck = sm + K2_A + k * 65;
        const u64 neg2 = pack2(-2.f, -2.f);
        #pragma unroll 4
        for (int e = 0; e < 64; e++) {
            float cv = ck[e];
            u64 cc = pack2(cv, cv);
            const u64* vv = (const u64*)(sm + K2_VT + e * 32 + pl0);
            #pragma unroll
            for (int i = 0; i < 8; i++) {
                u64 tt = cc;
                fma2(tt, neg2, vv[i]);
                fma2(d[i], cc, tt);
            }
        }
        float cwk = sm[K2_CW + k];
        float accA = 0.f, accB = 0.f;
        int bA = -1, bB = -1;
        #pragma unroll
        for (int i = 0; i < 8; i++) {
            float d0, d1; unpack2(d[i], d0, d1);
            #pragma unroll
            for (int s = 0; s < 2; s++) {
                int gp = pbase + pl0 + 2 * i + s;
                if (gp < NTOT) {
                    float dd = fmaxf(s == 0 ? d0 : d1, 0.f);
                    float owv = fmaxf(cwk * expf(-dd * inv_s2), 1e-10f);
                    int b = gp / NPP;
                    if (bA < 0 || b == bA) { bA = b; accA += owv; }
                    else                   { bB = b; accB += owv; }
                }
            }
        }
        if (bA >= 0) atomicAdd(&g_ysum[bA * 128 + k], accA);
        if (bB >= 0) atomicAdd(&g_ysum[bB * 128 + k], accB);
    }
}

/* ========== fin: normalize + project; self-zeroes g_ysum for replay ========== */
__global__ void fin_kernel(const float* __restrict__ c_y, float* __restrict__ out) {
    __shared__ float s_y[NB * 128];
    __shared__ float yv2[128 * 10];
    __shared__ float rsum[NB];
    int tid = threadIdx.x;
    for (int i = tid; i < NB * 128; i += blockDim.x) {
        s_y[i] = g_ysum[i];
        g_ysum[i] = 0.f;
    }
    __syncthreads();
    for (int k = tid; k < 128; k += blockDim.x) {
        float n2 = 0.f;
        for (int i = 0; i < 10; i++) { float c = c_y[k * 10 + i]; n2 = fmaf(c, c, n2); }
        float inv = 1.f / n2;
        for (int i = 0; i < 10; i++) { float c = c_y[k * 10 + i]; yv2[k * 10 + i] = c * c * inv; }
    }
    if (tid < NB) {
        float s = 0.f;
        for (int k = 0; k < 128; k++) s += s_y[tid * 128 + k];
        rsum[tid] = s;
    }
    __syncthreads();
    if (tid < NB * 10) {
        int b = tid / 10, i = tid % 10;
        float a = 0.f;
        for (int k = 0; k < 128; k++) a = fmaf(s_y[b * 128 + k], yv2[k * 10 + i], a);
        out[tid] = a / rsum[b];
    }
}

extern "C" void kernel_launch(void* const* d_in, const int* in_sizes, int n_in,
                              void* d_out, int out_size) {
    (void)in_sizes; (void)n_in; (void)out_size;
    const float* images = (const float*)d_in[0];
    const float* w1     = (const float*)d_in[1];
    const float* b1     = (const float*)d_in[2];
    const float* w2     = (const float*)d_in[3];
    const float* b2     = (const float*)d_in[4];
    const float* w3     = (const float*)d_in[5];
    const float* b3     = (const float*)d_in[6];
    const float* wd     = (const float*)d_in[7];
    const float* bd     = (const float*)d_in[8];
    const float* c_x    = (const float*)d_in[9];
    const float* c_y    = (const float*)d_in[10];
    const float* comp_w = (const float*)d_in[11];
    const float* sigma  = (const float*)d_in[12];
    float* out = (float*)d_out;

    cudaFuncSetAttribute(k1_kernel, cudaFuncAttributeMaxDynamicSharedMemorySize, K1_BYTES);
    cudaFuncSetAttribute(k2_kernel, cudaFuncAttributeMaxDynamicSharedMemorySize, K2_BYTES);

    k1_kernel<<<HALF1, T1, K1_BYTES>>>(images, w1, b1, w2, b2, 0);
    k1_kernel<<<HALF1, T1, K1_BYTES>>>(images, w1, b1, w2, b2, HALF1);
    k2_kernel<<<NBLK2, T2, K2_BYTES>>>(w3, b3, wd, bd, c_x, comp_w, sigma);
    fin_kernel<<<1, 256>>>(c_y, out);
}